// round 13
// baseline (speedup 1.0000x reference)
#include <cuda_runtime.h>
#include <math.h>

#define NROWS  4096
#define HALF   2048
#define DDIM   256
#define GROUPS 512            // NROWS / 8
#define TPB    384            // 12 warps = 3 features x 4 A-rows

__device__ float        g_groupsum[GROUPS];
__device__ unsigned int g_ticket;   // zero-initialized; last block resets it

__device__ __forceinline__ float warp_sum(float v) {
#pragma unroll
    for (int o = 16; o; o >>= 1) v += __shfl_xor_sync(0xFFFFFFFFu, v, o);
    return v;
}

// torchsort soft_rank (KL reg), n=4, strength=2 — log-free ratio form.
// B = LSE(s[i..j]) - LSE(logw[i..j]); dual_k = min_{i<=k} max_{j>=k} B;
// rank = exp(s - dual). log is monotone -> do max/min on R = Ssum/Wsum:
// rank_k = E_k / (min_i max_j R[i][j]),  E_k = exp(s_k - s_0).
__device__ __forceinline__ void soft_rank4(const float v[4], float out[4]) {
    float s[4];
    int perm[4] = {0, 1, 2, 3};
#pragma unroll
    for (int t = 0; t < 4; ++t) s[t] = v[t] * 0.5f;   // theta = v / strength

#define CSWAP(x, y)                                                     \
    if (s[x] < s[y]) {                                                  \
        float tf = s[x]; s[x] = s[y]; s[y] = tf;                        \
        int   ti = perm[x]; perm[x] = perm[y]; perm[y] = ti;            \
    }
    CSWAP(0, 1) CSWAP(2, 3) CSWAP(0, 2) CSWAP(1, 3) CSWAP(1, 2)
#undef CSWAP

    float E0 = 1.0f;
    float E1 = __expf(s[1] - s[0]);
    float E2 = __expf(s[2] - s[0]);
    float E3 = __expf(s[3] - s[0]);

    float S01 = E0 + E1, S12 = E1 + E2, S23 = E2 + E3;
    float S02 = S01 + E2, S13 = S12 + E3, S03 = S02 + E3;

    // w = [4,3,2,1] segment sums: 4,7,9,10 / 3,5,6 / 2,3 / 1
    float B00 = E0  * 0.25f;
    float B01 = S01 * (1.0f / 7.0f);
    float B02 = S02 * (1.0f / 9.0f);
    float B03 = S03 * 0.1f;
    float B11 = E1  * (1.0f / 3.0f);
    float B12 = S12 * 0.2f;
    float B13 = S13 * (1.0f / 6.0f);
    float B22 = E2  * 0.5f;
    float B23 = S23 * (1.0f / 3.0f);
    float B33 = E3;

    float M03 = B03, M02 = fmaxf(B02, M03), M01 = fmaxf(B01, M02), M00 = fmaxf(B00, M01);
    float M13 = B13, M12 = fmaxf(B12, M13), M11 = fmaxf(B11, M12);
    float M23 = B23, M22 = fmaxf(B22, M23);
    float M33 = B33;

    float R0 = M00;
    float R1 = fminf(M01, M11);
    float R2 = fminf(fminf(M02, M12), M22);
    float R3 = fminf(fminf(M03, M13), fminf(M23, M33));

    out[perm[0]] = __fdividef(E0, R0);
    out[perm[1]] = __fdividef(E1, R1);
    out[perm[2]] = __fdividef(E2, R2);
    out[perm[3]] = __fdividef(E3, R3);
}

__device__ __forceinline__ float spearman4(const float a[4], const float b[4]) {
    float ma = 0.25f * (a[0] + a[1] + a[2] + a[3]);
    float mb = 0.25f * (b[0] + b[1] + b[2] + b[3]);
    float na = 0.f, nb = 0.f, dp = 0.f;
#pragma unroll
    for (int t = 0; t < 4; ++t) {
        float x = a[t] - ma, y = b[t] - mb;
        na += x * x; nb += y * y; dp += x * y;
    }
    return dp * rsqrtf(na) * rsqrtf(nb);
}

// One block per id-group of 8 rows. 12 warps: warp (f,i) computes feature f,
// A-row i vs the 4 B rows. Whole tail stays in-block (smem). Only cross-block
// traffic: one group-sum store + one ticket atomic by tid 0.
__global__ __launch_bounds__(TPB) void fused_kernel(const float* __restrict__ f0,
                                                    const float* __restrict__ f1,
                                                    const float* __restrict__ f2,
                                                    float* __restrict__ out) {
    __shared__ float sh[3][8][DDIM];   // 24 KB
    __shared__ float dist[3][4][4];
    __shared__ float rloss[8];
    __shared__ float red[128];
    __shared__ int   is_last;

    int p    = blockIdx.x;
    int tid  = threadIdx.x;
    int w    = tid >> 5;
    int lane = tid & 31;

    const float* Fs[3] = {f0, f1, f2};

    // ---- load 1536 float4 (24 KB), 4 per thread; batch LDGs before STS ----
    float4 v[4];
    int cc[4], ff[4], rr_[4];
#pragma unroll
    for (int u = 0; u < 4; ++u) {
        int idx = tid + u * TPB;              // 0..1535
        int f   = idx >> 9;                   // 512 float4 per feature
        int rem = idx & 511;
        int r   = rem >> 6;                   // local row 0..7
        int c   = rem & 63;
        int grow = (r < 4) ? (4 * p + r) : (HALF + 4 * p + (r - 4));
        v[u] = ((const float4*)(Fs[f] + (size_t)grow * DDIM))[c];
        ff[u] = f; rr_[u] = r; cc[u] = c;
    }
#pragma unroll
    for (int u = 0; u < 4; ++u)
        ((float4*)&sh[ff[u]][rr_[u]][0])[cc[u]] = v[u];
    __syncthreads();

    // ---- distances: warp w -> feature f = w>>2, A-row i = w&3, vs B 0..3 ----
    {
        int f = w >> 2, i = w & 3;
        const float4* A = (const float4*)&sh[f][i][0];
        float4 a0 = A[lane], a1 = A[lane + 32];
        float s[4];
#pragma unroll
        for (int j = 0; j < 4; ++j) {
            const float4* B = (const float4*)&sh[f][4 + j][0];
            float4 b0 = B[lane], b1 = B[lane + 32];
            float dx0 = a0.x-b0.x, dy0 = a0.y-b0.y, dz0 = a0.z-b0.z, dw0 = a0.w-b0.w;
            float dx1 = a1.x-b1.x, dy1 = a1.y-b1.y, dz1 = a1.z-b1.z, dw1 = a1.w-b1.w;
            s[j] = dx0*dx0 + dy0*dy0 + dz0*dz0 + dw0*dw0
                 + dx1*dx1 + dy1*dy1 + dz1*dz1 + dw1*dw1;
        }
        // 4 independent reductions -> shfl chains overlap
#pragma unroll
        for (int j = 0; j < 4; ++j) s[j] = warp_sum(s[j]);
        if (lane == 0) {
#pragma unroll
            for (int j = 0; j < 4; ++j)
                dist[f][i][j] = sqrtf(fmaxf(s[j], 1e-12f));
        }
    }
    __syncthreads();

    // ---- tail: warps 0-7 own local rows; lanes 0-2 do the 3 soft-ranks ----
    if (w < 8) {
        int f = (lane < 3) ? lane : 0;
        float vv[4], rk[4];
#pragma unroll
        for (int k = 0; k < 4; ++k)
            vv[k] = (w < 4) ? dist[f][w][k] : dist[f][k][w - 4];
        soft_rank4(vv, rk);

        float r0[4], r1[4], r2[4];
#pragma unroll
        for (int k = 0; k < 4; ++k) {
            r0[k] = __shfl_sync(0xFFFFFFFFu, rk[k], 0);
            r1[k] = __shfl_sync(0xFFFFFFFFu, rk[k], 1);
            r2[k] = __shfl_sync(0xFFFFFFFFu, rk[k], 2);
        }
        if (lane == 0) {
            float c01 = spearman4(r0, r1);
            float c02 = spearman4(r0, r2);
            float c12 = spearman4(r1, r2);
            rloss[w] = (c01 + c02 + c12 + 3.0f) * (1.0f / 6.0f);
        }
    }
    __syncthreads();

    // ---- single-thread publish: store + release fence + ticket ----
    if (tid == 0) {
        float s = rloss[0] + rloss[1] + rloss[2] + rloss[3]
                + rloss[4] + rloss[5] + rloss[6] + rloss[7];
        g_groupsum[p] = s;             // tid 0 is the ONLY global-storing thread
        __threadfence();               // release (one thread, one block)
        unsigned int t = atomicAdd(&g_ticket, 1u);
        if (t == GROUPS - 1) __threadfence();   // acquire on the observer
        is_last = (t == GROUPS - 1);
    }
    __syncthreads();
    if (!is_last) return;

    // ---- last block: deterministic fixed-order tree over 512 group sums ----
    if (tid < 128) {
        float a = __ldcg(&g_groupsum[tid])       + __ldcg(&g_groupsum[tid + 128])
                + __ldcg(&g_groupsum[tid + 256]) + __ldcg(&g_groupsum[tid + 384]);
        red[tid] = a;
    }
    __syncthreads();
#pragma unroll
    for (int o = 64; o; o >>= 1) {
        if (tid < o) red[tid] += red[tid + o];
        __syncthreads();
    }
    if (tid == 0) {
        out[0]   = red[0] * (1.0f / NROWS);
        g_ticket = 0;                  // reset for next graph replay
    }
}

extern "C" void kernel_launch(void* const* d_in, const int* in_sizes, int n_in,
                              void* d_out, int out_size) {
    const float* f0 = (const float*)d_in[0];
    const float* f1 = (const float*)d_in[1];
    const float* f2 = (const float*)d_in[2];
    (void)in_sizes; (void)n_in; (void)out_size;

    fused_kernel<<<GROUPS, TPB>>>(f0, f1, f2, (float*)d_out);
}

// round 14
// speedup vs baseline: 1.0201x; 1.0201x over previous
#include <cuda_runtime.h>
#include <math.h>

#define NROWS  4096
#define HALF   2048
#define DDIM   256
#define GROUPS 512            // NROWS / 8
#define TPB    384            // 12 warps = 3 features x 4 A-rows
#define CELLS  64             // level-1 ticket cells (8 arrivals each)

__device__ float        g_groupsum[GROUPS];
__device__ unsigned int g_tick1[CELLS];   // level-1: spread addresses
__device__ unsigned int g_tick2;          // level-2: 64 arrivals only

__device__ __forceinline__ float warp_sum(float v) {
#pragma unroll
    for (int o = 16; o; o >>= 1) v += __shfl_xor_sync(0xFFFFFFFFu, v, o);
    return v;
}

// torchsort soft_rank (KL reg), n=4, strength=2 — log-free ratio form.
// B = LSE(s[i..j]) - LSE(logw[i..j]); dual_k = min_{i<=k} max_{j>=k} B;
// rank = exp(s - dual). log is monotone -> do max/min on R = Ssum/Wsum:
// rank_k = E_k / (min_i max_j R[i][j]),  E_k = exp(s_k - s_0).
__device__ __forceinline__ void soft_rank4(const float v[4], float out[4]) {
    float s[4];
    int perm[4] = {0, 1, 2, 3};
#pragma unroll
    for (int t = 0; t < 4; ++t) s[t] = v[t] * 0.5f;   // theta = v / strength

#define CSWAP(x, y)                                                     \
    if (s[x] < s[y]) {                                                  \
        float tf = s[x]; s[x] = s[y]; s[y] = tf;                        \
        int   ti = perm[x]; perm[x] = perm[y]; perm[y] = ti;            \
    }
    CSWAP(0, 1) CSWAP(2, 3) CSWAP(0, 2) CSWAP(1, 3) CSWAP(1, 2)
#undef CSWAP

    float E0 = 1.0f;
    float E1 = __expf(s[1] - s[0]);
    float E2 = __expf(s[2] - s[0]);
    float E3 = __expf(s[3] - s[0]);

    float S01 = E0 + E1, S12 = E1 + E2, S23 = E2 + E3;
    float S02 = S01 + E2, S13 = S12 + E3, S03 = S02 + E3;

    // w = [4,3,2,1] segment sums: 4,7,9,10 / 3,5,6 / 2,3 / 1
    float B00 = E0  * 0.25f;
    float B01 = S01 * (1.0f / 7.0f);
    float B02 = S02 * (1.0f / 9.0f);
    float B03 = S03 * 0.1f;
    float B11 = E1  * (1.0f / 3.0f);
    float B12 = S12 * 0.2f;
    float B13 = S13 * (1.0f / 6.0f);
    float B22 = E2  * 0.5f;
    float B23 = S23 * (1.0f / 3.0f);
    float B33 = E3;

    float M03 = B03, M02 = fmaxf(B02, M03), M01 = fmaxf(B01, M02), M00 = fmaxf(B00, M01);
    float M13 = B13, M12 = fmaxf(B12, M13), M11 = fmaxf(B11, M12);
    float M23 = B23, M22 = fmaxf(B22, M23);
    float M33 = B33;

    float R0 = M00;
    float R1 = fminf(M01, M11);
    float R2 = fminf(fminf(M02, M12), M22);
    float R3 = fminf(fminf(M03, M13), fminf(M23, M33));

    out[perm[0]] = __fdividef(E0, R0);
    out[perm[1]] = __fdividef(E1, R1);
    out[perm[2]] = __fdividef(E2, R2);
    out[perm[3]] = __fdividef(E3, R3);
}

__device__ __forceinline__ float spearman4(const float a[4], const float b[4]) {
    float ma = 0.25f * (a[0] + a[1] + a[2] + a[3]);
    float mb = 0.25f * (b[0] + b[1] + b[2] + b[3]);
    float na = 0.f, nb = 0.f, dp = 0.f;
#pragma unroll
    for (int t = 0; t < 4; ++t) {
        float x = a[t] - ma, y = b[t] - mb;
        na += x * x; nb += y * y; dp += x * y;
    }
    return dp * rsqrtf(na) * rsqrtf(nb);
}

// One block per id-group of 8 rows. Hierarchical arrival tickets:
// level 1 = 64 spread cells (8 arrivals each, parallel in L2),
// level 2 = one counter with only 64 arrivals. Last block reduces.
__global__ __launch_bounds__(TPB) void fused_kernel(const float* __restrict__ f0,
                                                    const float* __restrict__ f1,
                                                    const float* __restrict__ f2,
                                                    float* __restrict__ out) {
    __shared__ float sh[3][8][DDIM];   // 24 KB
    __shared__ float dist[3][4][4];
    __shared__ float rloss[8];
    __shared__ float red[4];
    __shared__ int   is_last;

    int p    = blockIdx.x;
    int tid  = threadIdx.x;
    int w    = tid >> 5;
    int lane = tid & 31;

    const float* Fs[3] = {f0, f1, f2};

    // ---- load 1536 float4 (24 KB), 4 per thread; batch LDGs before STS ----
    float4 v[4];
    int cc[4], ff[4], rr_[4];
#pragma unroll
    for (int u = 0; u < 4; ++u) {
        int idx = tid + u * TPB;              // 0..1535
        int f   = idx >> 9;                   // 512 float4 per feature
        int rem = idx & 511;
        int r   = rem >> 6;                   // local row 0..7
        int c   = rem & 63;
        int grow = (r < 4) ? (4 * p + r) : (HALF + 4 * p + (r - 4));
        v[u] = ((const float4*)(Fs[f] + (size_t)grow * DDIM))[c];
        ff[u] = f; rr_[u] = r; cc[u] = c;
    }
#pragma unroll
    for (int u = 0; u < 4; ++u)
        ((float4*)&sh[ff[u]][rr_[u]][0])[cc[u]] = v[u];
    __syncthreads();

    // ---- distances: warp w -> feature f = w>>2, A-row i = w&3, vs B 0..3 ----
    {
        int f = w >> 2, i = w & 3;
        const float4* A = (const float4*)&sh[f][i][0];
        float4 a0 = A[lane], a1 = A[lane + 32];
        float s[4];
#pragma unroll
        for (int j = 0; j < 4; ++j) {
            const float4* B = (const float4*)&sh[f][4 + j][0];
            float4 b0 = B[lane], b1 = B[lane + 32];
            float dx0 = a0.x-b0.x, dy0 = a0.y-b0.y, dz0 = a0.z-b0.z, dw0 = a0.w-b0.w;
            float dx1 = a1.x-b1.x, dy1 = a1.y-b1.y, dz1 = a1.z-b1.z, dw1 = a1.w-b1.w;
            s[j] = dx0*dx0 + dy0*dy0 + dz0*dz0 + dw0*dw0
                 + dx1*dx1 + dy1*dy1 + dz1*dz1 + dw1*dw1;
        }
#pragma unroll
        for (int j = 0; j < 4; ++j) s[j] = warp_sum(s[j]);
        if (lane == 0) {
#pragma unroll
            for (int j = 0; j < 4; ++j)
                dist[f][i][j] = sqrtf(fmaxf(s[j], 1e-12f));
        }
    }
    __syncthreads();

    // ---- tail: warps 0-7 own local rows; lanes 0-2 do the 3 soft-ranks ----
    if (w < 8) {
        int f = (lane < 3) ? lane : 0;
        float vv[4], rk[4];
#pragma unroll
        for (int k = 0; k < 4; ++k)
            vv[k] = (w < 4) ? dist[f][w][k] : dist[f][k][w - 4];
        soft_rank4(vv, rk);

        float r0[4], r1[4], r2[4];
#pragma unroll
        for (int k = 0; k < 4; ++k) {
            r0[k] = __shfl_sync(0xFFFFFFFFu, rk[k], 0);
            r1[k] = __shfl_sync(0xFFFFFFFFu, rk[k], 1);
            r2[k] = __shfl_sync(0xFFFFFFFFu, rk[k], 2);
        }
        if (lane == 0) {
            float c01 = spearman4(r0, r1);
            float c02 = spearman4(r0, r2);
            float c12 = spearman4(r1, r2);
            rloss[w] = (c01 + c02 + c12 + 3.0f) * (1.0f / 6.0f);
        }
    }
    __syncthreads();

    // ---- publish: store sum, release fence, HIERARCHICAL tickets ----
    if (tid == 0) {
        float s = rloss[0] + rloss[1] + rloss[2] + rloss[3]
                + rloss[4] + rloss[5] + rloss[6] + rloss[7];
        g_groupsum[p] = s;             // only global store from this block
        __threadfence();               // release before arrival
        int last = 0;
        unsigned int t1 = atomicAdd(&g_tick1[p & (CELLS - 1)], 1u);
        if (t1 == (GROUPS / CELLS) - 1) {          // cell complete (8th arriver)
            unsigned int t2 = atomicAdd(&g_tick2, 1u);
            if (t2 == CELLS - 1) {                 // all cells complete
                __threadfence();                   // acquire
                last = 1;
            }
        }
        is_last = last;
    }
    __syncthreads();
    if (!is_last) return;

    // ---- last block: deterministic fixed-order reduction of 512 sums ----
    // 384 threads: warps 0-3 each sum a fixed 128-element slice.
    if (w < 4) {
        float a = __ldcg(&g_groupsum[w * 128 + lane])
                + __ldcg(&g_groupsum[w * 128 + lane + 32])
                + __ldcg(&g_groupsum[w * 128 + lane + 64])
                + __ldcg(&g_groupsum[w * 128 + lane + 96]);
        a = warp_sum(a);
        if (lane == 0) red[w] = a;
    }
    // reset tickets for next graph replay
    if (tid < CELLS) g_tick1[tid] = 0;
    if (tid == 64)   g_tick2 = 0;
    __syncthreads();
    if (tid == 0)
        out[0] = (red[0] + red[1] + red[2] + red[3]) * (1.0f / NROWS);
}

extern "C" void kernel_launch(void* const* d_in, const int* in_sizes, int n_in,
                              void* d_out, int out_size) {
    const float* f0 = (const float*)d_in[0];
    const float* f1 = (const float*)d_in[1];
    const float* f2 = (const float*)d_in[2];
    (void)in_sizes; (void)n_in; (void)out_size;

    fused_kernel<<<GROUPS, TPB>>>(f0, f1, f2, (float*)d_out);
}